// round 7
// baseline (speedup 1.0000x reference)
#include <cuda_runtime.h>
#include <cuda_bf16.h>

#define DD 128
#define TILE_M 64
#define KC 32

// 51.2 MB scratch for support1 = X @ W1 (static device array: allowed, no alloc)
__device__ float g_s1[100000 * DD];

// ---------------------------------------------------------------------------
// k1 GEMM: efficient 64x128 tile, 4x8 per thread (96 regs OK here; FMA-bound,
// needs ILP not occupancy). Plain store to g_s1.
// ---------------------------------------------------------------------------
__device__ __forceinline__ void gemm_tile_fat(
    const float* __restrict__ X, const float* __restrict__ W,
    float* __restrict__ dst, int N, int bid)
{
    __shared__ float Xs[TILE_M][KC + 4];
    __shared__ float Ws[KC][DD];

    const int tid = threadIdx.x;
    const int tx = tid & 15;
    const int ty = tid >> 4;
    const int row0 = bid * TILE_M;

    float acc[4][8];
#pragma unroll
    for (int i = 0; i < 4; i++)
#pragma unroll
        for (int j = 0; j < 8; j++) acc[i][j] = 0.f;

    for (int kc = 0; kc < DD; kc += KC) {
        __syncthreads();
#pragma unroll
        for (int i = 0; i < 2; i++) {
            int idx = tid + i * 256;
            int r = idx >> 3;
            int q = idx & 7;
            int gr = row0 + r;
            if (gr >= N) gr = N - 1;
            *(float4*)&Xs[r][q * 4] =
                *(const float4*)&X[(long long)gr * DD + kc + q * 4];
        }
#pragma unroll
        for (int i = 0; i < 4; i++) {
            int idx = tid + i * 256;
            int r = idx >> 5;
            int q = idx & 31;
            *(float4*)&Ws[r][q * 4] = *(const float4*)&W[(kc + r) * DD + q * 4];
        }
        __syncthreads();

#pragma unroll
        for (int k = 0; k < KC; k++) {
            float a[4];
#pragma unroll
            for (int i = 0; i < 4; i++) a[i] = Xs[ty * 4 + i][k];
            float4 ba = *(float4*)&Ws[k][tx * 8];
            float4 bb = *(float4*)&Ws[k][tx * 8 + 4];
#pragma unroll
            for (int i = 0; i < 4; i++) {
                acc[i][0] += a[i] * ba.x; acc[i][1] += a[i] * ba.y;
                acc[i][2] += a[i] * ba.z; acc[i][3] += a[i] * ba.w;
                acc[i][4] += a[i] * bb.x; acc[i][5] += a[i] * bb.y;
                acc[i][6] += a[i] * bb.z; acc[i][7] += a[i] * bb.w;
            }
        }
    }

#pragma unroll
    for (int i = 0; i < 4; i++) {
        int gr = row0 + ty * 4 + i;
        if (gr < N) {
            long long base = (long long)gr * DD + tx * 8;
            *(float4*)&dst[base] =
                make_float4(acc[i][0], acc[i][1], acc[i][2], acc[i][3]);
            *(float4*)&dst[base + 4] =
                make_float4(acc[i][4], acc[i][5], acc[i][6], acc[i][7]);
        }
    }
}

// ---------------------------------------------------------------------------
// k1: blocks [0,G) compute g_s1 = X@W1. Blocks [G, G+ZB) fill out with bias.
// ---------------------------------------------------------------------------
__global__ __launch_bounds__(256) void k1_kernel(
    const float* __restrict__ X, const float* __restrict__ W1,
    const float* __restrict__ bias, float* __restrict__ out,
    int N, int G, int ZB)
{
    if ((int)blockIdx.x < G) {
        gemm_tile_fat(X, W1, g_s1, N, blockIdx.x);
    } else {
        int zb = blockIdx.x - G;
        int tid = threadIdx.x;
        float4 bv = *(const float4*)&bias[(tid & 31) * 4];
        size_t total4 = (size_t)N * (DD / 4);
        for (size_t i = (size_t)zb * 256 + tid; i < total4;
             i += (size_t)ZB * 256)
            ((float4*)out)[i] = bv;   // stride multiple of 32 keeps col fixed
    }
}

// ---------------------------------------------------------------------------
// k2: blocks [0,EB): edge aggregation (warp-batched, red.add.v4).
//     blocks [EB,..): lean 32x128 GEMM tile, out += X@W0 (red epilogue).
// Register-lean so edge occupancy isn't throttled: launch_bounds(256,5).
// ---------------------------------------------------------------------------
#define TM2 32
__global__ __launch_bounds__(256, 5) void k2_kernel(
    const float* __restrict__ X, const float* __restrict__ W0,
    const int* __restrict__ ei, const float* __restrict__ ev,
    float* __restrict__ out, int N, int E, int EB)
{
    if ((int)blockIdx.x >= EB) {
        // ---- lean GEMM: 32 rows x 128 cols, 2x8 per thread ----
        __shared__ float Xs[TM2][KC + 4];
        __shared__ float Ws[KC][DD];

        const int tid = threadIdx.x;
        const int tx = tid & 15;
        const int ty = tid >> 4;
        const int row0 = (blockIdx.x - EB) * TM2;

        float acc[2][8];
#pragma unroll
        for (int i = 0; i < 2; i++)
#pragma unroll
            for (int j = 0; j < 8; j++) acc[i][j] = 0.f;

        for (int kc = 0; kc < DD; kc += KC) {
            __syncthreads();
            {   // X tile: 32 rows x 32 cols = 256 float4, 1 per thread
                int r = tid >> 3;
                int q = tid & 7;
                int gr = row0 + r;
                if (gr >= N) gr = N - 1;
                *(float4*)&Xs[r][q * 4] =
                    *(const float4*)&X[(long long)gr * DD + kc + q * 4];
            }
#pragma unroll
            for (int i = 0; i < 4; i++) {
                int idx = tid + i * 256;
                int r = idx >> 5;
                int q = idx & 31;
                *(float4*)&Ws[r][q * 4] =
                    *(const float4*)&W0[(kc + r) * DD + q * 4];
            }
            __syncthreads();

#pragma unroll
            for (int k = 0; k < KC; k++) {
                float a0 = Xs[ty * 2][k];
                float a1 = Xs[ty * 2 + 1][k];
                float4 ba = *(float4*)&Ws[k][tx * 8];
                float4 bb = *(float4*)&Ws[k][tx * 8 + 4];
                acc[0][0] += a0 * ba.x; acc[0][1] += a0 * ba.y;
                acc[0][2] += a0 * ba.z; acc[0][3] += a0 * ba.w;
                acc[0][4] += a0 * bb.x; acc[0][5] += a0 * bb.y;
                acc[0][6] += a0 * bb.z; acc[0][7] += a0 * bb.w;
                acc[1][0] += a1 * ba.x; acc[1][1] += a1 * ba.y;
                acc[1][2] += a1 * ba.z; acc[1][3] += a1 * ba.w;
                acc[1][4] += a1 * bb.x; acc[1][5] += a1 * bb.y;
                acc[1][6] += a1 * bb.z; acc[1][7] += a1 * bb.w;
            }
        }

#pragma unroll
        for (int i = 0; i < 2; i++) {
            int gr = row0 + ty * 2 + i;
            if (gr < N) {
                long long base = (long long)gr * DD + tx * 8;
                float* p0 = out + base;
                float* p1 = out + base + 4;
                asm volatile("red.global.add.v4.f32 [%0], {%1,%2,%3,%4};"
                             :: "l"(p0), "f"(acc[i][0]), "f"(acc[i][1]),
                                "f"(acc[i][2]), "f"(acc[i][3]) : "memory");
                asm volatile("red.global.add.v4.f32 [%0], {%1,%2,%3,%4};"
                             :: "l"(p1), "f"(acc[i][4]), "f"(acc[i][5]),
                                "f"(acc[i][6]), "f"(acc[i][7]) : "memory");
            }
        }
        return;
    }

    // ---- edge aggregation: one warp per 32-edge batch ----
    const int lane = threadIdx.x & 31;
    int wglob = blockIdx.x * 8 + (threadIdx.x >> 5);
    int e0 = wglob * 32;
    if (e0 >= E) return;

    int e = e0 + lane;
    bool valid = e < E;
    int src = valid ? __ldg(&ei[e]) : 0;
    int dst = valid ? __ldg(&ei[E + e]) : 0;
    float a = valid ? __ldg(&ev[e]) : 0.f;   // a=0 => red adds 0: harmless

    const unsigned FULL = 0xffffffffu;
#pragma unroll 1
    for (int j0 = 0; j0 < 32; j0 += 4) {
        float4 v[4];
        int d[4];
        float s[4];
#pragma unroll
        for (int jj = 0; jj < 4; jj++) {
            int j = j0 + jj;
            int sj = __shfl_sync(FULL, src, j);
            d[jj] = __shfl_sync(FULL, dst, j);
            s[jj] = __shfl_sync(FULL, a, j);
            v[jj] = *(const float4*)(g_s1 + (size_t)sj * DD + lane * 4);
        }
#pragma unroll
        for (int jj = 0; jj < 4; jj++) {
            float4 t = v[jj];
            float sc = s[jj];
            t.x *= sc; t.y *= sc; t.z *= sc; t.w *= sc;
            float* p = out + (size_t)d[jj] * DD + lane * 4;
            asm volatile("red.global.add.v4.f32 [%0], {%1,%2,%3,%4};"
                         :: "l"(p), "f"(t.x), "f"(t.y), "f"(t.z), "f"(t.w)
                         : "memory");
        }
    }
}

extern "C" void kernel_launch(void* const* d_in, const int* in_sizes, int n_in,
                              void* d_out, int out_size)
{
    const float* X    = (const float*)d_in[0];   // [N,128] f32
    const int*   ei   = (const int*)d_in[1];     // [2,E] int32
    const float* ev   = (const float*)d_in[2];   // [E] f32
    const float* W0   = (const float*)d_in[3];   // [128,128] f32
    const float* W1   = (const float*)d_in[4];   // [128,128] f32
    const float* bias = (const float*)d_in[5];   // [128] f32
    float* out = (float*)d_out;

    int N = in_sizes[0] / DD;
    int E = in_sizes[2];

    int G1 = (N + TILE_M - 1) / TILE_M;          // 1563 fat tiles (W1)
    int ZB = 512;                                 // bias-fill blocks

    // k1: g_s1 = X@W1  ||  out = bias (broadcast fill)
    k1_kernel<<<G1 + ZB, 256>>>(X, W1, bias, out, N, G1, ZB);

    // k2: edges first (longer pole), lean W0-GEMM blocks behind them
    int EB = (E + 32 * 8 - 1) / (32 * 8);         // 6250 edge blocks
    int G2 = (N + TM2 - 1) / TM2;                 // 3125 lean tiles (W0)
    k2_kernel<<<EB + G2, 256>>>(X, W0, ei, ev, out, N, E, EB);
}

// round 8
// speedup vs baseline: 1.2994x; 1.2994x over previous
#include <cuda_runtime.h>
#include <cuda_bf16.h>

#define DD 128
#define TILE_M 64
#define KC 32

// 51.2 MB scratch for support1 = X @ W1 (static device array: allowed, no alloc)
__device__ float g_s1[100000 * DD];

// ---------------------------------------------------------------------------
// k1: fused dual GEMM. out = X@W0 + bias, g_s1 = X@W1. 64x128 tile,
// 256 threads, 4x8 per thread per matrix. X tile loads shared by both GEMMs.
// (R2-proven: ~232 us, FMA-bound.)
// ---------------------------------------------------------------------------
__global__ __launch_bounds__(256) void gemm2_kernel(
    const float* __restrict__ X, const float* __restrict__ W0,
    const float* __restrict__ W1, const float* __restrict__ bias,
    float* __restrict__ out, int N)
{
    __shared__ float Xs[TILE_M][KC + 4];
    __shared__ float W0s[KC][DD];
    __shared__ float W1s[KC][DD];

    const int tid = threadIdx.x;
    const int tx = tid & 15;
    const int ty = tid >> 4;
    const int row0 = blockIdx.x * TILE_M;

    float acc0[4][8];
    float acc1[4][8];
#pragma unroll
    for (int i = 0; i < 4; i++)
#pragma unroll
        for (int j = 0; j < 8; j++) { acc0[i][j] = 0.f; acc1[i][j] = 0.f; }

    for (int kc = 0; kc < DD; kc += KC) {
        __syncthreads();
#pragma unroll
        for (int i = 0; i < 2; i++) {
            int idx = tid + i * 256;
            int r = idx >> 3;
            int q = idx & 7;
            int gr = row0 + r;
            if (gr >= N) gr = N - 1;
            *(float4*)&Xs[r][q * 4] =
                *(const float4*)&X[(long long)gr * DD + kc + q * 4];
        }
#pragma unroll
        for (int i = 0; i < 4; i++) {
            int idx = tid + i * 256;
            int r = idx >> 5;
            int q = idx & 31;
            *(float4*)&W0s[r][q * 4] = *(const float4*)&W0[(kc + r) * DD + q * 4];
            *(float4*)&W1s[r][q * 4] = *(const float4*)&W1[(kc + r) * DD + q * 4];
        }
        __syncthreads();

#pragma unroll
        for (int k = 0; k < KC; k++) {
            float a[4];
#pragma unroll
            for (int i = 0; i < 4; i++) a[i] = Xs[ty * 4 + i][k];
            float4 b0a = *(float4*)&W0s[k][tx * 8];
            float4 b0b = *(float4*)&W0s[k][tx * 8 + 4];
            float4 b1a = *(float4*)&W1s[k][tx * 8];
            float4 b1b = *(float4*)&W1s[k][tx * 8 + 4];
#pragma unroll
            for (int i = 0; i < 4; i++) {
                acc0[i][0] += a[i] * b0a.x; acc0[i][1] += a[i] * b0a.y;
                acc0[i][2] += a[i] * b0a.z; acc0[i][3] += a[i] * b0a.w;
                acc0[i][4] += a[i] * b0b.x; acc0[i][5] += a[i] * b0b.y;
                acc0[i][6] += a[i] * b0b.z; acc0[i][7] += a[i] * b0b.w;
                acc1[i][0] += a[i] * b1a.x; acc1[i][1] += a[i] * b1a.y;
                acc1[i][2] += a[i] * b1a.z; acc1[i][3] += a[i] * b1a.w;
                acc1[i][4] += a[i] * b1b.x; acc1[i][5] += a[i] * b1b.y;
                acc1[i][6] += a[i] * b1b.z; acc1[i][7] += a[i] * b1b.w;
            }
        }
    }

    float4 bq0 = *(const float4*)&bias[tx * 8];
    float4 bq1 = *(const float4*)&bias[tx * 8 + 4];

#pragma unroll
    for (int i = 0; i < 4; i++) {
        int gr = row0 + ty * 4 + i;
        if (gr < N) {
            long long base = (long long)gr * DD + tx * 8;
            *(float4*)&out[base] =
                make_float4(acc0[i][0] + bq0.x, acc0[i][1] + bq0.y,
                            acc0[i][2] + bq0.z, acc0[i][3] + bq0.w);
            *(float4*)&out[base + 4] =
                make_float4(acc0[i][4] + bq1.x, acc0[i][5] + bq1.y,
                            acc0[i][6] + bq1.z, acc0[i][7] + bq1.w);
            *(float4*)&g_s1[base] =
                make_float4(acc1[i][0], acc1[i][1], acc1[i][2], acc1[i][3]);
            *(float4*)&g_s1[base + 4] =
                make_float4(acc1[i][4], acc1[i][5], acc1[i][6], acc1[i][7]);
        }
    }
}

// ---------------------------------------------------------------------------
// k2: standalone warp-batched edge aggregation.
// One warp per 32-edge batch: coalesced src/dst/val loads (3 loads per 32
// edges), then 4-deep gather->red pipeline. red.add.v4.f32 into out.
// ---------------------------------------------------------------------------
__global__ __launch_bounds__(256) void edge_kernel(
    const int* __restrict__ ei, const float* __restrict__ ev,
    float* __restrict__ out, int E)
{
    const int lane = threadIdx.x & 31;
    int wglob = blockIdx.x * 8 + (threadIdx.x >> 5);
    int e0 = wglob * 32;
    if (e0 >= E) return;

    int e = e0 + lane;
    bool valid = e < E;
    int src = valid ? __ldg(&ei[e]) : 0;
    int dst = valid ? __ldg(&ei[E + e]) : 0;
    float a = valid ? __ldg(&ev[e]) : 0.f;   // a=0 => red adds 0: harmless

    const unsigned FULL = 0xffffffffu;
#pragma unroll 1
    for (int j0 = 0; j0 < 32; j0 += 4) {
        float4 v[4];
        int d[4];
        float s[4];
#pragma unroll
        for (int jj = 0; jj < 4; jj++) {
            int j = j0 + jj;
            int sj = __shfl_sync(FULL, src, j);
            d[jj] = __shfl_sync(FULL, dst, j);
            s[jj] = __shfl_sync(FULL, a, j);
            v[jj] = *(const float4*)(g_s1 + (size_t)sj * DD + lane * 4);
        }
#pragma unroll
        for (int jj = 0; jj < 4; jj++) {
            float4 t = v[jj];
            float sc = s[jj];
            t.x *= sc; t.y *= sc; t.z *= sc; t.w *= sc;
            float* p = out + (size_t)d[jj] * DD + lane * 4;
            asm volatile("red.global.add.v4.f32 [%0], {%1,%2,%3,%4};"
                         :: "l"(p), "f"(t.x), "f"(t.y), "f"(t.z), "f"(t.w)
                         : "memory");
        }
    }
}

extern "C" void kernel_launch(void* const* d_in, const int* in_sizes, int n_in,
                              void* d_out, int out_size)
{
    const float* X    = (const float*)d_in[0];   // [N,128] f32
    const int*   ei   = (const int*)d_in[1];     // [2,E] int32
    const float* ev   = (const float*)d_in[2];   // [E] f32
    const float* W0   = (const float*)d_in[3];   // [128,128] f32
    const float* W1   = (const float*)d_in[4];   // [128,128] f32
    const float* bias = (const float*)d_in[5];   // [128] f32
    float* out = (float*)d_out;

    int N = in_sizes[0] / DD;
    int E = in_sizes[2];

    // k1: out = X@W0 + bias, g_s1 = X@W1 (X tiles shared)
    gemm2_kernel<<<(N + TILE_M - 1) / TILE_M, 256>>>(X, W0, W1, bias, out, N);

    // k2: out[dst] += ev * g_s1[src], warp-batched
    int EB = (E + 32 * 8 - 1) / (32 * 8);        // 6250 blocks
    edge_kernel<<<EB, 256>>>(ei, ev, out, E);
}

// round 10
// speedup vs baseline: 1.6388x; 1.2611x over previous
#include <cuda_runtime.h>
#include <cuda_bf16.h>
#include <cstdint>

#define DD 128

// 51.2 MB scratch for support1 = X @ W1 (static device array: allowed, no alloc)
__device__ float g_s1[100000 * DD];

// ---------------------------------------------------------------------------
// TF32 helpers
// ---------------------------------------------------------------------------
__device__ __forceinline__ uint32_t cvt_tf32(float x) {
    uint32_t u;
    asm("cvt.rna.tf32.f32 %0, %1;" : "=r"(u) : "f"(x));
    return u;
}
// x -> hi (tf32-exact) + lo (tf32-rounded residual)
__device__ __forceinline__ void split_tf32(float x, float& hi, float& lo) {
    uint32_t uh = cvt_tf32(x);
    hi = __uint_as_float(uh);
    lo = __uint_as_float(cvt_tf32(x - hi));
}
__device__ __forceinline__ void split4(float4 v, float4& h, float4& l) {
    split_tf32(v.x, h.x, l.x); split_tf32(v.y, h.y, l.y);
    split_tf32(v.z, h.z, l.z); split_tf32(v.w, h.w, l.w);
}

#define MMA_TF32(d, a, b)                                                     \
    asm volatile(                                                             \
        "mma.sync.aligned.m16n8k8.row.col.f32.tf32.tf32.f32 "                 \
        "{%0,%1,%2,%3},{%4,%5,%6,%7},{%8,%9},{%0,%1,%2,%3};"                  \
        : "+f"((d)[0]), "+f"((d)[1]), "+f"((d)[2]), "+f"((d)[3])              \
        : "r"((a)[0]), "r"((a)[1]), "r"((a)[2]), "r"((a)[3]),                 \
          "r"((b)[0]), "r"((b)[1]))

// smem layout (floats)
#define XS_STRIDE 36       // 128 rows x 32 cols (padded) ; 144B/row
#define WS_STRIDE 136      // 32 rows x 128 cols (padded) ; 544B/row
#define XS_ELEMS (128 * XS_STRIDE)   // 4608
#define WS_ELEMS (32 * WS_STRIDE)    // 4352
#define SMEM_FLOATS (2 * XS_ELEMS + 2 * WS_ELEMS)   // 17920
#define SMEM_BYTES  (SMEM_FLOATS * 4)               // 71680

// ---------------------------------------------------------------------------
// 3xTF32 GEMM: one 128x128 output tile per block.
// blockIdx.y == 0: dst = out = X@W0 + bias ; blockIdx.y == 1: dst = g_s1 = X@W1
// 8 warps: warpM = wid&3 (32 rows), warpN = wid>>2 (64 cols).
// Each warp: 2 (m16) x 8 (n8) mma tiles, 3 MMAs per tile per k8 (hh, hl, lh).
// ---------------------------------------------------------------------------
__global__ __launch_bounds__(256) void gemm_tf32_kernel(
    const float* __restrict__ X, const float* __restrict__ W0,
    const float* __restrict__ W1, const float* __restrict__ bias,
    float* __restrict__ out, int N)
{
    extern __shared__ float sm[];
    float* Xh = sm;
    float* Xl = Xh + XS_ELEMS;
    float* Wh = Xl + XS_ELEMS;
    float* Wl = Wh + WS_ELEMS;

    const float* W = (blockIdx.y == 0) ? W0 : W1;

    const int tid   = threadIdx.x;
    const int lane  = tid & 31;
    const int gid   = lane >> 2;       // 0..7
    const int tig   = lane & 3;        // 0..3
    const int wid   = tid >> 5;
    const int rbase = (wid & 3) * 32;  // warpM * 32
    const int nbase = (wid >> 2) * 64; // warpN * 64
    const int row0  = blockIdx.x * 128;

    float cd[2][8][4];
#pragma unroll
    for (int mt = 0; mt < 2; mt++)
#pragma unroll
        for (int nt = 0; nt < 8; nt++)
#pragma unroll
            for (int j = 0; j < 4; j++) cd[mt][nt][j] = 0.f;

    for (int kc = 0; kc < DD; kc += 32) {
        __syncthreads();
        // X chunk: 128x32 = 1024 float4, 4 per thread; split hi/lo on fill
#pragma unroll
        for (int i = 0; i < 4; i++) {
            int idx = tid + i * 256;
            int r = idx >> 3;          // 0..127
            int q = idx & 7;           // 0..7
            int gr = row0 + r;
            if (gr >= N) gr = N - 1;
            float4 v = *(const float4*)&X[(size_t)gr * DD + kc + q * 4];
            float4 h, l;
            split4(v, h, l);
            int o = r * XS_STRIDE + q * 4;
            *(float4*)&Xh[o] = h;
            *(float4*)&Xl[o] = l;
        }
        // W chunk: 32x128 = 1024 float4, 4 per thread
#pragma unroll
        for (int i = 0; i < 4; i++) {
            int idx = tid + i * 256;
            int r = idx >> 5;          // 0..31
            int q = idx & 31;          // 0..31
            float4 v = *(const float4*)&W[(kc + r) * DD + q * 4];
            float4 h, l;
            split4(v, h, l);
            int o = r * WS_STRIDE + q * 4;
            *(float4*)&Wh[o] = h;
            *(float4*)&Wl[o] = l;
        }
        __syncthreads();

#pragma unroll
        for (int k8 = 0; k8 < 4; k8++) {
            const int kk = k8 * 8;
            uint32_t ah[2][4], al[2][4];
#pragma unroll
            for (int mt = 0; mt < 2; mt++) {
                int r  = rbase + mt * 16 + gid;
                int c0 = kk + tig;
                int c1 = kk + tig + 4;
                ah[mt][0] = __float_as_uint(Xh[r * XS_STRIDE + c0]);
                ah[mt][1] = __float_as_uint(Xh[(r + 8) * XS_STRIDE + c0]);
                ah[mt][2] = __float_as_uint(Xh[r * XS_STRIDE + c1]);
                ah[mt][3] = __float_as_uint(Xh[(r + 8) * XS_STRIDE + c1]);
                al[mt][0] = __float_as_uint(Xl[r * XS_STRIDE + c0]);
                al[mt][1] = __float_as_uint(Xl[(r + 8) * XS_STRIDE + c0]);
                al[mt][2] = __float_as_uint(Xl[r * XS_STRIDE + c1]);
                al[mt][3] = __float_as_uint(Xl[(r + 8) * XS_STRIDE + c1]);
            }
#pragma unroll
            for (int nt = 0; nt < 8; nt++) {
                int ncol = nbase + nt * 8 + gid;
                uint32_t bh[2], bl[2];
                bh[0] = __float_as_uint(Wh[(kk + tig) * WS_STRIDE + ncol]);
                bh[1] = __float_as_uint(Wh[(kk + tig + 4) * WS_STRIDE + ncol]);
                bl[0] = __float_as_uint(Wl[(kk + tig) * WS_STRIDE + ncol]);
                bl[1] = __float_as_uint(Wl[(kk + tig + 4) * WS_STRIDE + ncol]);
#pragma unroll
                for (int mt = 0; mt < 2; mt++) {
                    MMA_TF32(cd[mt][nt], ah[mt], bh);   // hi*hi
                    MMA_TF32(cd[mt][nt], ah[mt], bl);   // hi*lo
                    MMA_TF32(cd[mt][nt], al[mt], bh);   // lo*hi
                }
            }
        }
    }

    float* dst = (blockIdx.y == 0) ? out : g_s1;
    const bool addb = (blockIdx.y == 0);

#pragma unroll
    for (int nt = 0; nt < 8; nt++) {
        int col = nbase + nt * 8 + tig * 2;
        float b0 = addb ? bias[col] : 0.f;
        float b1 = addb ? bias[col + 1] : 0.f;
#pragma unroll
        for (int mt = 0; mt < 2; mt++) {
            int r0 = row0 + rbase + mt * 16 + gid;
            int r1 = r0 + 8;
            if (r0 < N) {
                float2 t = make_float2(cd[mt][nt][0] + b0, cd[mt][nt][1] + b1);
                *(float2*)&dst[(size_t)r0 * DD + col] = t;
            }
            if (r1 < N) {
                float2 t = make_float2(cd[mt][nt][2] + b0, cd[mt][nt][3] + b1);
                *(float2*)&dst[(size_t)r1 * DD + col] = t;
            }
        }
    }
}

// ---------------------------------------------------------------------------
// Edge aggregation (R8-proven, 154 us): one warp per 32-edge batch, coalesced
// index loads, 4-deep gather->red pipeline, red.add.v4.f32 into out.
// ---------------------------------------------------------------------------
__global__ __launch_bounds__(256) void edge_kernel(
    const int* __restrict__ ei, const float* __restrict__ ev,
    float* __restrict__ out, int E)
{
    const int lane = threadIdx.x & 31;
    int wglob = blockIdx.x * 8 + (threadIdx.x >> 5);
    int e0 = wglob * 32;
    if (e0 >= E) return;

    int e = e0 + lane;
    bool valid = e < E;
    int src = valid ? __ldg(&ei[e]) : 0;
    int dst = valid ? __ldg(&ei[E + e]) : 0;
    float a = valid ? __ldg(&ev[e]) : 0.f;   // a=0 => red adds 0: harmless

    const unsigned FULL = 0xffffffffu;
#pragma unroll 1
    for (int j0 = 0; j0 < 32; j0 += 4) {
        float4 v[4];
        int d[4];
        float s[4];
#pragma unroll
        for (int jj = 0; jj < 4; jj++) {
            int j = j0 + jj;
            int sj = __shfl_sync(FULL, src, j);
            d[jj] = __shfl_sync(FULL, dst, j);
            s[jj] = __shfl_sync(FULL, a, j);
            v[jj] = *(const float4*)(g_s1 + (size_t)sj * DD + lane * 4);
        }
#pragma unroll
        for (int jj = 0; jj < 4; jj++) {
            float4 t = v[jj];
            float sc = s[jj];
            t.x *= sc; t.y *= sc; t.z *= sc; t.w *= sc;
            float* p = out + (size_t)d[jj] * DD + lane * 4;
            asm volatile("red.global.add.v4.f32 [%0], {%1,%2,%3,%4};"
                         :: "l"(p), "f"(t.x), "f"(t.y), "f"(t.z), "f"(t.w)
                         : "memory");
        }
    }
}

extern "C" void kernel_launch(void* const* d_in, const int* in_sizes, int n_in,
                              void* d_out, int out_size)
{
    const float* X    = (const float*)d_in[0];   // [N,128] f32
    const int*   ei   = (const int*)d_in[1];     // [2,E] int32
    const float* ev   = (const float*)d_in[2];   // [E] f32
    const float* W0   = (const float*)d_in[3];   // [128,128] f32
    const float* W1   = (const float*)d_in[4];   // [128,128] f32
    const float* bias = (const float*)d_in[5];   // [128] f32
    float* out = (float*)d_out;

    int N = in_sizes[0] / DD;
    int E = in_sizes[2];

    // Allow 70 KB dynamic smem (host API; idempotent; capture-legal)
    cudaFuncSetAttribute(gemm_tf32_kernel,
                         cudaFuncAttributeMaxDynamicSharedMemorySize, SMEM_BYTES);

    // k1: 3xTF32 tensor-core dual GEMM (y=0: out=X@W0+bias, y=1: g_s1=X@W1)
    int GX = (N + 127) / 128;
    gemm_tf32_kernel<<<dim3(GX, 2), 256, SMEM_BYTES>>>(X, W0, W1, bias, out, N);

    // k2: out[dst] += ev * g_s1[src], warp-batched
    int EB = (E + 32 * 8 - 1) / (32 * 8);        // 6250 blocks
    edge_kernel<<<EB, 256>>>(ei, ev, out, E);
}